// round 1
// baseline (speedup 1.0000x reference)
#include <cuda_runtime.h>

#define H 128
#define W 128
#define HW 16384

// ---------------- device scratch (no allocations allowed) ----------------
__device__ float g_off[4 * 10 * HW];       // conv1 output, channels 0..9 only
__device__ float g_mu[20];                 // GN1 mean  per (b, group0..4)
__device__ float g_rstd[20];               // GN1 rstd
__device__ float g_ymap[4 * 9 * HW];       // clipped y coordinate per (b,k,h,w)
__device__ float g_pre[4 * 64 * HW];       // conv2 output pre-GN
__device__ float g_part[4 * 128 * 16 * 2]; // per-(b,h,group) partial sum/sumsq
__device__ float g_mr[128];                // final GN mean/rstd per (b,group)

// ---------------- kernel 1: 3x3 conv, 64 -> 10 channels ------------------
__global__ void __launch_bounds__(128) k_conv1(const float* __restrict__ x,
                                               const float* __restrict__ w_off,
                                               const float* __restrict__ b_off) {
    __shared__ float ws[64 * 90]; // [cin][c(10)][t(9)]
    int h = blockIdx.x, b = blockIdx.y, w = threadIdx.x;
    for (int i = threadIdx.x; i < 64 * 90; i += 128) {
        int cin = i / 90, r = i - cin * 90;
        int c = r / 9, t = r - c * 9;
        ws[i] = w_off[(c * 64 + cin) * 9 + t];
    }
    __syncthreads();

    float acc[10];
#pragma unroll
    for (int c = 0; c < 10; c++) acc[c] = b_off[c];

    const float* xb = x + b * 64 * HW;
    for (int cin = 0; cin < 64; ++cin) {
        float v[9];
#pragma unroll
        for (int dy = 0; dy < 3; ++dy) {
            int hy = h + dy - 1;
            const float* row = xb + cin * HW + hy * W;
            bool hv = (hy >= 0 && hy < H);
#pragma unroll
            for (int dx = 0; dx < 3; ++dx) {
                int wx = w + dx - 1;
                v[dy * 3 + dx] = (hv && wx >= 0 && wx < W) ? row[wx] : 0.f;
            }
        }
        const float* wp = ws + cin * 90;
#pragma unroll
        for (int c = 0; c < 10; c++)
#pragma unroll
            for (int t = 0; t < 9; t++)
                acc[c] = fmaf(v[t], wp[c * 9 + t], acc[c]);
    }
    int base = b * 10 * HW + h * W + w;
#pragma unroll
    for (int c = 0; c < 10; c++) g_off[base + c * HW] = acc[c];
}

// ---------------- kernel 2: GN1 stats (groups of 2 channels) -------------
__global__ void __launch_bounds__(256) k_gn1_stats() {
    int bg = blockIdx.x;          // 0..19 : b*5+g
    int b = bg / 5, g = bg - b * 5;
    const float* p = g_off + (b * 10 + 2 * g) * HW;
    float s = 0.f, q = 0.f;
    for (int i = threadIdx.x; i < 2 * HW; i += 256) {
        float v = p[i];
        s += v; q += v * v;
    }
    __shared__ float rs[256], rq[256];
    int tid = threadIdx.x;
    rs[tid] = s; rq[tid] = q;
    __syncthreads();
    for (int st = 128; st > 0; st >>= 1) {
        if (tid < st) { rs[tid] += rs[tid + st]; rq[tid] += rq[tid + st]; }
        __syncthreads();
    }
    if (tid == 0) {
        float mu = rs[0] / 32768.f;
        float var = rq[0] / 32768.f - mu * mu;
        g_mu[bg] = mu;
        g_rstd[bg] = rsqrtf(var + 1e-5f);
    }
}

// --------- kernel 3: normalize + tanh + cumsum -> y coordinate map -------
__global__ void __launch_bounds__(256) k_offsets(const float* __restrict__ gam,
                                                 const float* __restrict__ bet) {
    int pix = blockIdx.x * 256 + threadIdx.x;   // 65536 pixels
    int b = pix >> 14, hw = pix & 16383;
    int h = hw >> 7;

    float t[10];
#pragma unroll
    for (int c = 0; c < 10; c++) {
        float v = g_off[(b * 10 + c) * HW + hw];
        int g = c >> 1;
        v = (v - g_mu[b * 5 + g]) * g_rstd[b * 5 + g];
        t[c] = tanhf(v * gam[c] + bet[c]);
    }
    float yn[9];
    yn[3] = t[3];
    yn[2] = t[2] + yn[3];
    yn[1] = t[1] + yn[2];
    yn[0] = t[0] + yn[1];
    yn[4] = 0.f;
    yn[5] = t[5];
    yn[6] = yn[5] + t[6];
    yn[7] = yn[6] + t[7];
    yn[8] = yn[7] + t[8];
#pragma unroll
    for (int k = 0; k < 9; k++) {
        float yc = fminf(fmaxf((float)h + yn[k], 0.f), 127.f);
        g_ymap[((b * 9 + k) << 14) + hw] = yc;
    }
}

// 16B-unit XOR swizzle for conflict-free LDS.128 in the GEMM phase
__device__ __forceinline__ int swz(int w) {
    int u = w >> 2;
    return (((u ^ (u >> 3)) << 2) | (w & 3));
}

// --------- kernel 4: fused sampling + 9x1 strided conv (the big one) -----
// grid (h=128, b=4), 256 threads. thread: co = tid>>2 (0..63), wsub = tid&3
// (32 consecutive w). Accumulators as packed f32x2 (fma.rn.f32x2, full rate).
__global__ void __launch_bounds__(256, 2) k_fused(const float* __restrict__ x,
                                                  const float* __restrict__ w_dsc,
                                                  const float* __restrict__ b_dsc) {
    extern __shared__ float sm[];
    float* s    = sm;                       // 16*9*128 = 18432 floats (swizzled)
    float* wys  = sm + 18432;               // 1152
    int*   y0s  = (int*)(sm + 18432 + 1152);// 1152
    float* redS = sm + 18432 + 2304;        // 256
    float* redQ = redS + 256;               // 256

    int h = blockIdx.x, b = blockIdx.y;
    int tid = threadIdx.x;

    // phase A: decode y coordinates for this (b,h) row: 9*128 entries
    for (int e = tid; e < 1152; e += 256) {
        int k = e >> 7, w = e & 127;
        float yc = g_ymap[((b * 9 + k) << 14) + (h << 7) + w];
        int y0 = (int)yc;                  // yc in [0,127] -> trunc == floor
        y0s[e] = y0;
        wys[e] = yc - (float)y0;
    }

    unsigned long long acc[16];            // 32 fp32 accumulators, packed
#pragma unroll
    for (int i = 0; i < 16; i++) acc[i] = 0ull;

    int co = tid >> 2, wsub = tid & 3;
    const float* wrow = w_dsc + co * 576;  // [cin][9]
    int wb = wsub << 3;                    // 16B-unit base within a 128-float row

    for (int c4 = 0; c4 < 4; ++c4) {       // cin chunks of 16
        __syncthreads();
        // fill s[ci][k][w] = sampled deformed value (linear interp in y only;
        // x coordinate is exactly integer so wx == 0)
        const float* xb = x + ((b * 64 + c4 * 16) << 14);
        for (int e = tid; e < 16 * 1152; e += 256) {
            int ci = e / 1152;
            int r = e - ci * 1152;
            int k = r >> 7, w = r & 127;
            int xw = w + k - 4;
            xw = max(0, min(127, xw));
            int y0 = y0s[r];
            float wy = wys[r];
            int y1 = min(y0 + 1, 127);
            const float* xc = xb + (ci << 14);
            float v0 = xc[(y0 << 7) + xw];
            float v1 = xc[(y1 << 7) + xw];
            s[ci * 1152 + k * 128 + swz(w)] = v0 + wy * (v1 - v0);
        }
        __syncthreads();

        const float* wchunk = wrow + c4 * 16 * 9;
#pragma unroll 1
        for (int ci = 0; ci < 16; ++ci) {
            const ulonglong2* sp16 = (const ulonglong2*)(s + ci * 1152);
#pragma unroll
            for (int k = 0; k < 9; ++k) {
                float wt = __ldg(&wchunk[ci * 9 + k]);
                unsigned long long wt2;
                asm("mov.b64 %0, {%1, %1};" : "=l"(wt2) : "f"(wt));
                const ulonglong2* sk = sp16 + k * 32; // 128 floats = 32 x 16B
#pragma unroll
                for (int j = 0; j < 8; ++j) {
                    ulonglong2 v = sk[wb + (j ^ wsub)];
                    asm("fma.rn.f32x2 %0, %1, %2, %0;"
                        : "+l"(acc[2 * j]) : "l"(v.x), "l"(wt2));
                    asm("fma.rn.f32x2 %0, %1, %2, %0;"
                        : "+l"(acc[2 * j + 1]) : "l"(v.y), "l"(wt2));
                }
            }
        }
    }

    // epilogue: bias, store pre-GN, deterministic per-block partial stats
    float bias = b_dsc[co];
    float lsum = 0.f, lsq = 0.f;
    float* outp = g_pre + ((b * 64 + co) << 14) + (h << 7) + wsub * 32;
#pragma unroll
    for (int p = 0; p < 16; ++p) {
        union { unsigned long long u; float2 f; } cv;
        cv.u = acc[p];
        float o0 = cv.f.x + bias;
        float o1 = cv.f.y + bias;
        float2 st; st.x = o0; st.y = o1;
        *(float2*)(outp + 2 * p) = st;
        lsum += o0 + o1;
        lsq += o0 * o0 + o1 * o1;
    }
    redS[tid] = lsum;
    redQ[tid] = lsq;
    __syncthreads();
    if (tid < 16) { // threads [g*16, g*16+16) all have group == g (co>>2)
        float ss = 0.f, qq = 0.f;
#pragma unroll
        for (int i = 0; i < 16; ++i) {
            ss += redS[tid * 16 + i];
            qq += redQ[tid * 16 + i];
        }
        int idx = (((b << 7) + h) * 16 + tid) * 2;
        g_part[idx] = ss;
        g_part[idx + 1] = qq;
    }
}

// --------- kernel 5: reduce partials -> final GN mean/rstd ----------------
__global__ void k_gn2_reduce() {
    int bg = threadIdx.x;                  // 64 threads
    if (bg >= 64) return;
    int b = bg >> 4, g = bg & 15;
    float s = 0.f, q = 0.f;
    for (int hh = 0; hh < 128; ++hh) {
        int idx = (((b << 7) + hh) * 16 + g) * 2;
        s += g_part[idx];
        q += g_part[idx + 1];
    }
    float mu = s / 65536.f;
    float var = q / 65536.f - mu * mu;
    g_mr[bg * 2] = mu;
    g_mr[bg * 2 + 1] = rsqrtf(var + 1e-5f);
}

// --------- kernel 6: normalize + relu -> output ---------------------------
__global__ void __launch_bounds__(256) k_final(const float* __restrict__ gam,
                                               const float* __restrict__ bet,
                                               float* __restrict__ out) {
    int i = blockIdx.x * 256 + threadIdx.x; // 4194304
    int c = (i >> 14) & 63;
    int b = i >> 20;
    int bg = (b << 4) + (c >> 2);
    float mu = g_mr[bg * 2], rs = g_mr[bg * 2 + 1];
    float v = g_pre[i];
    float o = (v - mu) * rs * gam[c] + bet[c];
    out[i] = fmaxf(o, 0.f);
}

// -------------------------------------------------------------------------
extern "C" void kernel_launch(void* const* d_in, const int* in_sizes, int n_in,
                              void* d_out, int out_size) {
    const float* x        = (const float*)d_in[0];
    const float* w_off    = (const float*)d_in[1];
    const float* b_off    = (const float*)d_in[2];
    const float* g_gn_off = (const float*)d_in[3];
    const float* b_gn_off = (const float*)d_in[4];
    const float* w_dsc    = (const float*)d_in[5];
    const float* b_dsc    = (const float*)d_in[6];
    const float* g_gn     = (const float*)d_in[7];
    const float* b_gn     = (const float*)d_in[8];
    float* out = (float*)d_out;

    k_conv1<<<dim3(128, 4), 128>>>(x, w_off, b_off);
    k_gn1_stats<<<20, 256>>>();
    k_offsets<<<256, 256>>>(g_gn_off, b_gn_off);

    int smem4 = (18432 + 1152 + 1152 + 512) * 4; // 84992 bytes
    cudaFuncSetAttribute(k_fused, cudaFuncAttributeMaxDynamicSharedMemorySize, smem4);
    k_fused<<<dim3(128, 4), 256, smem4>>>(x, w_dsc, b_dsc);

    k_gn2_reduce<<<1, 64>>>();
    k_final<<<16384, 256>>>(g_gn, b_gn, out);
}

// round 3
// speedup vs baseline: 2.0598x; 2.0598x over previous
#include <cuda_runtime.h>

#define H 128
#define W 128
#define HW 16384

// ---------------- device scratch (no allocations allowed) ----------------
__device__ float g_off[4 * 10 * HW];       // conv1 output, channels 0..9 only
__device__ float g_mu[20];                 // GN1 mean  per (b, group0..4)
__device__ float g_rstd[20];               // GN1 rstd
__device__ float g_ymap[4 * 9 * HW];       // clipped y coordinate per (b,k,h,w)
__device__ float g_pre[4 * 64 * HW];       // conv2 output pre-GN
__device__ float g_part[4 * 128 * 16 * 2]; // per-(b,h,group) partial sum/sumsq
__device__ float g_mr[128];                // final GN mean/rstd per (b,group)
__device__ float g_wT[576 * 64];           // transposed conv2 weights [ci*9+k][co]

// ---------------- kernel 0: transpose conv2 weights ----------------------
__global__ void k_wtr(const float* __restrict__ w_dsc) {
    int i = blockIdx.x * 256 + threadIdx.x;    // 36864
    int co = i / 576;
    int r = i - co * 576;                      // ci*9+k
    g_wT[r * 64 + co] = w_dsc[i];
}

// ---------------- kernel 1: 3x3 conv, 64 -> 10 channels (packed f32x2) ---
__global__ void __launch_bounds__(128) k_conv1(const float* __restrict__ x,
                                               const float* __restrict__ w_off,
                                               const float* __restrict__ b_off) {
    __shared__ float ws[64 * 90]; // [cin][t(9)][c(10)] -> channel pairs 8B aligned
    int h = blockIdx.x, b = blockIdx.y, w = threadIdx.x;
    for (int i = threadIdx.x; i < 64 * 90; i += 128) {
        int cin = i / 90, r = i - cin * 90;
        int t = r / 10, c = r - t * 10;
        ws[i] = w_off[(c * 64 + cin) * 9 + t];
    }
    __syncthreads();

    unsigned long long acc[5];
#pragma unroll
    for (int j = 0; j < 5; j++) {
        float b0 = b_off[2 * j], b1 = b_off[2 * j + 1];
        asm("mov.b64 %0,{%1,%2};" : "=l"(acc[j]) : "f"(b0), "f"(b1));
    }

    const float* xb = x + b * 64 * HW;
    for (int cin = 0; cin < 64; ++cin) {
        float v[9];
#pragma unroll
        for (int dy = 0; dy < 3; ++dy) {
            int hy = h + dy - 1;
            const float* row = xb + cin * HW + hy * W;
            bool hv = (hy >= 0 && hy < H);
#pragma unroll
            for (int dx = 0; dx < 3; ++dx) {
                int wx = w + dx - 1;
                v[dy * 3 + dx] = (hv && wx >= 0 && wx < W) ? row[wx] : 0.f;
            }
        }
        const unsigned long long* wp2 = (const unsigned long long*)(ws + cin * 90);
#pragma unroll
        for (int t = 0; t < 9; t++) {
            unsigned long long vv;
            asm("mov.b64 %0,{%1,%1};" : "=l"(vv) : "f"(v[t]));
#pragma unroll
            for (int j = 0; j < 5; j++) {
                unsigned long long wpair = wp2[t * 5 + j];
                asm("fma.rn.f32x2 %0, %1, %2, %0;"
                    : "+l"(acc[j]) : "l"(vv), "l"(wpair));
            }
        }
    }
    int base = b * 10 * HW + h * W + w;
#pragma unroll
    for (int j = 0; j < 5; j++) {
        union { unsigned long long u; float2 f; } cv;
        cv.u = acc[j];
        g_off[base + (2 * j) * HW] = cv.f.x;
        g_off[base + (2 * j + 1) * HW] = cv.f.y;
    }
}

// ---------------- kernel 2: GN1 stats (groups of 2 channels) -------------
__global__ void __launch_bounds__(256) k_gn1_stats() {
    int bg = blockIdx.x;          // 0..19 : b*5+g
    int b = bg / 5, g = bg - b * 5;
    const float* p = g_off + (b * 10 + 2 * g) * HW;
    float s = 0.f, q = 0.f;
    for (int i = threadIdx.x; i < 2 * HW; i += 256) {
        float v = p[i];
        s += v; q += v * v;
    }
    __shared__ float rs[256], rq[256];
    int tid = threadIdx.x;
    rs[tid] = s; rq[tid] = q;
    __syncthreads();
    for (int st = 128; st > 0; st >>= 1) {
        if (tid < st) { rs[tid] += rs[tid + st]; rq[tid] += rq[tid + st]; }
        __syncthreads();
    }
    if (tid == 0) {
        float mu = rs[0] / 32768.f;
        float var = rq[0] / 32768.f - mu * mu;
        g_mu[bg] = mu;
        g_rstd[bg] = rsqrtf(var + 1e-5f);
    }
}

// --------- kernel 3: normalize + tanh + cumsum -> y coordinate map -------
__global__ void __launch_bounds__(256) k_offsets(const float* __restrict__ gam,
                                                 const float* __restrict__ bet) {
    int pix = blockIdx.x * 256 + threadIdx.x;   // 65536 pixels
    int b = pix >> 14, hw = pix & 16383;
    int h = hw >> 7;

    float t[10];
#pragma unroll
    for (int c = 0; c < 10; c++) {
        float v = g_off[(b * 10 + c) * HW + hw];
        int g = c >> 1;
        v = (v - g_mu[b * 5 + g]) * g_rstd[b * 5 + g];
        t[c] = tanhf(v * gam[c] + bet[c]);
    }
    float yn[9];
    yn[3] = t[3];
    yn[2] = t[2] + yn[3];
    yn[1] = t[1] + yn[2];
    yn[0] = t[0] + yn[1];
    yn[4] = 0.f;
    yn[5] = t[5];
    yn[6] = yn[5] + t[6];
    yn[7] = yn[6] + t[7];
    yn[8] = yn[7] + t[8];
#pragma unroll
    for (int k = 0; k < 9; k++) {
        float yc = fminf(fmaxf((float)h + yn[k], 0.f), 127.f);
        g_ymap[((b * 9 + k) << 14) + hw] = yc;
    }
}

// 16B-line XOR swizzle: line u = w>>2, u' = u ^ ((u>>3)&3)
__device__ __forceinline__ int swz(int w) {
    int u = w >> 2;
    return (((u ^ ((u >> 3) & 3)) << 2) | (w & 3));
}

// --------- kernel 4: fused sampling + 9x1 strided conv (the big one) -----
// grid (h=128, b=4), 256 threads, 3 CTAs/SM.
// thread: cg = tid>>4 -> output channels cg*4..cg*4+3 (= GN group cg),
//         wg = tid&15 -> w = wg*8..wg*8+7.
// Per (ci,k): 2 LDS.128 data + 1 LDG.128 weights + 16 fma.rn.f32x2.
__global__ void __launch_bounds__(256, 3) k_fused(const float* __restrict__ x,
                                                  const float* __restrict__ b_dsc) {
    extern __shared__ float sm[];
    float* s    = sm;                        // 8*1152 = 9216 floats (swizzled)
    float* wys  = sm + 9216;                 // 1152
    int*   y0s  = (int*)(sm + 10368);        // 1152
    float* redS = sm + 11520;                // 256
    float* redQ = sm + 11776;                // 256

    int h = blockIdx.x, b = blockIdx.y;
    int tid = threadIdx.x;
    int cg = tid >> 4, wg = tid & 15;

    // phase A: decode y coordinates for this (b,h) row: 9*128 entries
    for (int e = tid; e < 1152; e += 256) {
        int k = e >> 7, w = e & 127;
        float yc = g_ymap[((b * 9 + k) << 14) + (h << 7) + w];
        int y0 = (int)yc;                    // yc in [0,127] -> trunc == floor
        y0s[e] = y0;
        wys[e] = yc - (float)y0;
    }

    unsigned long long acc[16];              // [co(4)][wpair(4)]
#pragma unroll
    for (int i = 0; i < 16; i++) acc[i] = 0ull;

    // swizzled 16B-line indices for this thread's 8 w
    int u0 = wg * 2;
    int su0 = u0 ^ ((u0 >> 3) & 3);
    int u1 = u0 + 1;
    int su1 = u1 ^ ((u1 >> 3) & 3);

    for (int c8 = 0; c8 < 8; ++c8) {         // cin chunks of 8
        __syncthreads();
        // fill s[ci][k][w] = sampled value (linear interp in y only; x coord
        // is exactly integer so wx == 0)
        const float* xb = x + ((b * 64 + c8 * 8) << 14);
        for (int e = tid; e < 9216; e += 256) {
            int ci = e / 1152;
            int r = e - ci * 1152;
            int k = r >> 7, w = r & 127;
            int xw = min(127, max(0, w + k - 4));
            int y0 = y0s[r];
            float wy = wys[r];
            int y1 = min(y0 + 1, 127);
            const float* xc = xb + (ci << 14);
            float v0 = xc[(y0 << 7) + xw];
            float v1 = xc[(y1 << 7) + xw];
            s[ci * 1152 + k * 128 + swz(w)] = v0 + wy * (v1 - v0);
        }
        __syncthreads();

#pragma unroll 1
        for (int ci = 0; ci < 8; ++ci) {
            const float4* wrow = (const float4*)g_wT + ((c8 * 8 + ci) * 9) * 16 + cg;
            const float* srow = s + ci * 1152;
#pragma unroll
            for (int k = 0; k < 9; ++k) {
                float4 wv = __ldg(wrow + k * 16);
                unsigned long long w0, w1, w2, w3;
                asm("mov.b64 %0,{%1,%1};" : "=l"(w0) : "f"(wv.x));
                asm("mov.b64 %0,{%1,%1};" : "=l"(w1) : "f"(wv.y));
                asm("mov.b64 %0,{%1,%1};" : "=l"(w2) : "f"(wv.z));
                asm("mov.b64 %0,{%1,%1};" : "=l"(w3) : "f"(wv.w));
                const ulonglong2* sk = (const ulonglong2*)(srow + k * 128);
                ulonglong2 va = sk[su0];
                ulonglong2 vb = sk[su1];
                asm("fma.rn.f32x2 %0, %1, %2, %0;" : "+l"(acc[0])  : "l"(va.x), "l"(w0));
                asm("fma.rn.f32x2 %0, %1, %2, %0;" : "+l"(acc[1])  : "l"(va.y), "l"(w0));
                asm("fma.rn.f32x2 %0, %1, %2, %0;" : "+l"(acc[2])  : "l"(vb.x), "l"(w0));
                asm("fma.rn.f32x2 %0, %1, %2, %0;" : "+l"(acc[3])  : "l"(vb.y), "l"(w0));
                asm("fma.rn.f32x2 %0, %1, %2, %0;" : "+l"(acc[4])  : "l"(va.x), "l"(w1));
                asm("fma.rn.f32x2 %0, %1, %2, %0;" : "+l"(acc[5])  : "l"(va.y), "l"(w1));
                asm("fma.rn.f32x2 %0, %1, %2, %0;" : "+l"(acc[6])  : "l"(vb.x), "l"(w1));
                asm("fma.rn.f32x2 %0, %1, %2, %0;" : "+l"(acc[7])  : "l"(vb.y), "l"(w1));
                asm("fma.rn.f32x2 %0, %1, %2, %0;" : "+l"(acc[8])  : "l"(va.x), "l"(w2));
                asm("fma.rn.f32x2 %0, %1, %2, %0;" : "+l"(acc[9])  : "l"(va.y), "l"(w2));
                asm("fma.rn.f32x2 %0, %1, %2, %0;" : "+l"(acc[10]) : "l"(vb.x), "l"(w2));
                asm("fma.rn.f32x2 %0, %1, %2, %0;" : "+l"(acc[11]) : "l"(vb.y), "l"(w2));
                asm("fma.rn.f32x2 %0, %1, %2, %0;" : "+l"(acc[12]) : "l"(va.x), "l"(w3));
                asm("fma.rn.f32x2 %0, %1, %2, %0;" : "+l"(acc[13]) : "l"(va.y), "l"(w3));
                asm("fma.rn.f32x2 %0, %1, %2, %0;" : "+l"(acc[14]) : "l"(vb.x), "l"(w3));
                asm("fma.rn.f32x2 %0, %1, %2, %0;" : "+l"(acc[15]) : "l"(vb.y), "l"(w3));
            }
        }
    }

    // epilogue: bias, store pre-GN, deterministic partial stats (group == cg)
    float lsum = 0.f, lsq = 0.f;
#pragma unroll
    for (int co = 0; co < 4; ++co) {
        float bias = b_dsc[cg * 4 + co];
        float o[8];
#pragma unroll
        for (int p = 0; p < 4; ++p) {
            union { unsigned long long u; float2 f; } cv;
            cv.u = acc[co * 4 + p];
            o[2 * p] = cv.f.x + bias;
            o[2 * p + 1] = cv.f.y + bias;
        }
        float* outp = g_pre + ((b * 64 + cg * 4 + co) << 14) + (h << 7) + wg * 8;
        float4 s0; s0.x = o[0]; s0.y = o[1]; s0.z = o[2]; s0.w = o[3];
        float4 s1; s1.x = o[4]; s1.y = o[5]; s1.z = o[6]; s1.w = o[7];
        *(float4*)(outp) = s0;
        *(float4*)(outp + 4) = s1;
#pragma unroll
        for (int p = 0; p < 8; ++p) { lsum += o[p]; lsq += o[p] * o[p]; }
    }
    redS[tid] = lsum;
    redQ[tid] = lsq;
    __syncthreads();
    if (tid < 16) { // threads [g*16, g*16+16) all belong to GN group g
        float ss = 0.f, qq = 0.f;
#pragma unroll
        for (int i = 0; i < 16; ++i) {
            ss += redS[tid * 16 + i];
            qq += redQ[tid * 16 + i];
        }
        int idx = (((b << 7) + h) * 16 + tid) * 2;
        g_part[idx] = ss;
        g_part[idx + 1] = qq;
    }
}

// --------- kernel 5: reduce partials -> final GN mean/rstd ----------------
__global__ void k_gn2_reduce() {
    int bg = threadIdx.x;                  // 64 threads
    if (bg >= 64) return;
    int b = bg >> 4, g = bg & 15;
    float s = 0.f, q = 0.f;
    for (int hh = 0; hh < 128; ++hh) {
        int idx = (((b << 7) + hh) * 16 + g) * 2;
        s += g_part[idx];
        q += g_part[idx + 1];
    }
    float mu = s / 65536.f;
    float var = q / 65536.f - mu * mu;
    g_mr[bg * 2] = mu;
    g_mr[bg * 2 + 1] = rsqrtf(var + 1e-5f);
}

// --------- kernel 6: normalize + relu -> output (float4) ------------------
__global__ void __launch_bounds__(256) k_final(const float* __restrict__ gam,
                                               const float* __restrict__ bet,
                                               float* __restrict__ out) {
    int i4 = blockIdx.x * 256 + threadIdx.x;   // 1048576 float4s
    int i = i4 * 4;
    int c = (i >> 14) & 63;
    int b = i >> 20;
    int bg = (b << 4) + (c >> 2);
    float mu = g_mr[bg * 2], rs = g_mr[bg * 2 + 1];
    float ga = gam[c] * rs, be = bet[c] - mu * ga;
    float4 v = *(const float4*)(g_pre + i);
    float4 o;
    o.x = fmaxf(fmaf(v.x, ga, be), 0.f);
    o.y = fmaxf(fmaf(v.y, ga, be), 0.f);
    o.z = fmaxf(fmaf(v.z, ga, be), 0.f);
    o.w = fmaxf(fmaf(v.w, ga, be), 0.f);
    *(float4*)(out + i) = o;
}

// -------------------------------------------------------------------------
extern "C" void kernel_launch(void* const* d_in, const int* in_sizes, int n_in,
                              void* d_out, int out_size) {
    const float* x        = (const float*)d_in[0];
    const float* w_off    = (const float*)d_in[1];
    const float* b_off    = (const float*)d_in[2];
    const float* g_gn_off = (const float*)d_in[3];
    const float* b_gn_off = (const float*)d_in[4];
    const float* w_dsc    = (const float*)d_in[5];
    const float* b_dsc    = (const float*)d_in[6];
    const float* g_gn     = (const float*)d_in[7];
    const float* b_gn     = (const float*)d_in[8];
    float* out = (float*)d_out;

    k_wtr<<<144, 256>>>(w_dsc);
    k_conv1<<<dim3(128, 4), 128>>>(x, w_off, b_off);
    k_gn1_stats<<<20, 256>>>();
    k_offsets<<<256, 256>>>(g_gn_off, b_gn_off);

    int smem4 = 12032 * 4; // 48128 bytes (<= 48KB default limit)
    k_fused<<<dim3(128, 4), 256, smem4>>>(x, b_dsc);

    k_gn2_reduce<<<1, 64>>>();
    k_final<<<4096, 256>>>(g_gn, b_gn, out);
}